// round 4
// baseline (speedup 1.0000x reference)
#include <cuda_runtime.h>

// AutogradLoss: loss = (x-y)^2, d_loss = 2(x-y), sqd_loss = 2*I per sample (constant).
// Output layout: [loss (B*16) | d_loss (B*16) | sqd_loss (B*256)] floats.
// Pure HBM-bound: 134 MB reads + 1.208 GB writes. Goal: uniform ~7.3+ TB/s.

// ---- loss + d_loss: 4 float4 per thread, block-strided for coalescing ----
__global__ void __launch_bounds__(256) loss_grad_kernel(
        const float4* __restrict__ x,
        const float4* __restrict__ y,
        float4* __restrict__ loss,
        float4* __restrict__ dloss,
        int n4) {
    int base = blockIdx.x * (256 * 4) + threadIdx.x;
    float4 a[4], b[4];
    int idx[4];
    bool ok[4];
    // Front-batch all loads (MLP=8)
    #pragma unroll
    for (int j = 0; j < 4; j++) {
        idx[j] = base + j * 256;
        ok[j] = idx[j] < n4;
        if (ok[j]) {
            a[j] = __ldcs(&x[idx[j]]);
            b[j] = __ldcs(&y[idx[j]]);
        }
    }
    #pragma unroll
    for (int j = 0; j < 4; j++) {
        if (ok[j]) {
            float dx = a[j].x - b[j].x, dy = a[j].y - b[j].y;
            float dz = a[j].z - b[j].z, dw = a[j].w - b[j].w;
            float4 l = make_float4(dx * dx, dy * dy, dz * dz, dw * dw);
            float4 g = make_float4(2.f * dx, 2.f * dy, 2.f * dz, 2.f * dw);
            __stcs(&loss[idx[j]], l);
            __stcs(&dloss[idx[j]], g);
        }
    }
}

// ---- sqd_loss = 2*I per sample. 8 float4 per thread, block-strided. ----
// float4 index i: flat float offset = 4*i. Within-sample offset s0 = (i & 63)*4.
// row = s0>>4 (constant across the 4 lanes), col0 = s0&15.
// Element e (e=0..3) is 2.0f iff row == col0+e.
__global__ void __launch_bounds__(256) hess_kernel(float4* __restrict__ sq,
                                                   long long n4) {
    long long base = (long long)blockIdx.x * (256 * 8) + threadIdx.x;
    #pragma unroll
    for (int j = 0; j < 8; j++) {
        long long i = base + j * 256;
        if (i < n4) {
            int s0 = ((int)i & 63) << 2;   // flat offset of .x within sample (0..252)
            int row = s0 >> 4;
            int col0 = s0 & 15;
            float4 v;
            v.x = (row == col0)     ? 2.0f : 0.0f;
            v.y = (row == col0 + 1) ? 2.0f : 0.0f;
            v.z = (row == col0 + 2) ? 2.0f : 0.0f;
            v.w = (row == col0 + 3) ? 2.0f : 0.0f;
            __stcs(&sq[i], v);   // streaming: write-once, never re-read
        }
    }
}

extern "C" void kernel_launch(void* const* d_in, const int* in_sizes, int n_in,
                              void* d_out, int out_size) {
    const float* x = (const float*)d_in[0];
    const float* y = (const float*)d_in[1];
    float* out = (float*)d_out;

    long long bd = in_sizes[0];          // B*16
    long long n4_ld = bd / 4;            // float4 count for loss / d_loss
    long long n4_sq = bd * 16 / 4;       // float4 count for sqd_loss

    float* loss  = out;
    float* dloss = out + bd;
    float* sq    = out + 2 * bd;

    {
        long long per_block = 256LL * 4;
        int blocks = (int)((n4_ld + per_block - 1) / per_block);
        loss_grad_kernel<<<blocks, 256>>>((const float4*)x, (const float4*)y,
                                          (float4*)loss, (float4*)dloss,
                                          (int)n4_ld);
    }
    {
        long long per_block = 256LL * 8;
        int blocks = (int)((n4_sq + per_block - 1) / per_block);
        hess_kernel<<<blocks, 256>>>((float4*)sq, n4_sq);
    }
}